// round 1
// baseline (speedup 1.0000x reference)
#include <cuda_runtime.h>
#include <math.h>

#define BB   4096
#define NN   32
#define DA   16
#define DOBS 64
#define HH   256
#define BN   (BB*NN)
#define TM   64
#define SPAD 68
#define LN32 3.4657359027997265f
#define LR   0.1f

// ---------------- device scratch (static, no runtime allocation) ----------------
__device__ float g_pre1[BN*HH];    // obs @ W1_obs  (step-invariant)
__device__ float g_abuf[BN*DA];    // current actions
__device__ float g_score[BN*DA];   // dq/da
__device__ float g_logp[BN];       // accumulated logp
__device__ float g_w2t[HH*HH];     // W2 transposed

// ---------------- init: a -> abuf, logp -> 0 ----------------
__global__ void init_kernel(const float* __restrict__ a)
{
    int i = blockIdx.x * 256 + threadIdx.x;
    if (i < BN*DA) g_abuf[i] = a[i];
    if (i < BN)    g_logp[i] = 0.f;
}

// ---------------- W2 transpose (256x256) ----------------
__global__ void transpose_w2(const float* __restrict__ w2)
{
    __shared__ float t[32][33];
    int x  = blockIdx.x * 32 + threadIdx.x;
    int y0 = blockIdx.y * 32;
    for (int i = threadIdx.y; i < 32; i += 8)
        t[i][threadIdx.x] = w2[(y0 + i) * HH + x];
    __syncthreads();
    int x2 = blockIdx.y * 32 + threadIdx.x;
    for (int i = threadIdx.y; i < 32; i += 8)
        g_w2t[(blockIdx.x * 32 + i) * HH + x2] = t[threadIdx.x][i];
}

// ---------------- pre1 = obs @ W1[0:64,:]  (once per launch) ----------------
__global__ void __launch_bounds__(256, 1) pre1_kernel(const float* __restrict__ obs,
                                                      const float* __restrict__ w1)
{
    __shared__ float osT[DOBS*SPAD];   // [d][r], padded
    const int tid  = threadIdx.x;
    const int c    = tid;
    const int row0 = blockIdx.x * TM;

    for (int idx = tid; idx < TM*DOBS; idx += 256) {
        int r = idx >> 6, d = idx & 63;
        osT[d*SPAD + r] = obs[(row0 + r) * DOBS + d];
    }
    __syncthreads();

    float acc[TM];
#pragma unroll
    for (int r = 0; r < TM; r++) acc[r] = 0.f;

#pragma unroll 1
    for (int d0 = 0; d0 < DOBS; d0 += 8) {
        float wv[8];
#pragma unroll
        for (int u = 0; u < 8; u++) wv[u] = w1[(d0 + u) * HH + c];
#pragma unroll
        for (int u = 0; u < 8; u++) {
            const float4* hp = (const float4*)&osT[(d0 + u) * SPAD];
#pragma unroll
            for (int r4 = 0; r4 < 16; r4++) {
                float4 h = hp[r4];
                acc[4*r4+0] = fmaf(h.x, wv[u], acc[4*r4+0]);
                acc[4*r4+1] = fmaf(h.y, wv[u], acc[4*r4+1]);
                acc[4*r4+2] = fmaf(h.z, wv[u], acc[4*r4+2]);
                acc[4*r4+3] = fmaf(h.w, wv[u], acc[4*r4+3]);
            }
        }
    }
#pragma unroll
    for (int r = 0; r < TM; r++) g_pre1[(row0 + r) * HH + c] = acc[r];
}

// ---------------- fused MLP forward + backward ----------------
// 64 rows per block, 256 threads (1 thread = 1 hidden column)
// SMEM: h1sT[256][68] | g2sT[256][68] | g1rm[64][256] | as[64][16] | qpart[8][64]
#define SMEM_FLOATS (HH*SPAD + HH*SPAD + TM*HH + TM*DA + 8*TM)
#define SMEM_BYTES  (SMEM_FLOATS * 4)

__global__ void __launch_bounds__(256, 1) mlp_kernel(
    const float* __restrict__ w1, const float* __restrict__ b1,
    const float* __restrict__ w2, const float* __restrict__ b2,
    const float* __restrict__ w3, const float* __restrict__ b3,
    float* __restrict__ q_out)
{
    extern __shared__ float sm[];
    float* h1sT  = sm;                    // [k=256][r=64] pad 68, post-relu h1 (later g1 mask source)
    float* g2sT  = h1sT + HH*SPAD;        // [k][r]
    float* g1rm  = g2sT + HH*SPAD;        // [r][j=256]
    float* as    = g1rm + TM*HH;          // [r][16]
    float* qpart = as + TM*DA;            // [warp][r]

    const int tid  = threadIdx.x;
    const int c    = tid;
    const int lane = tid & 31, wid = tid >> 5;
    const int row0 = blockIdx.x * TM;

    for (int idx = tid; idx < TM*DA; idx += 256) as[idx] = g_abuf[row0*DA + idx];
    __syncthreads();

    float acc[TM];

    // ---- Phase A: h1 = relu(pre1 + a @ W1_act + b1), column c ----
#pragma unroll
    for (int r = 0; r < TM; r++) acc[r] = g_pre1[(row0 + r) * HH + c];
#pragma unroll
    for (int d = 0; d < DA; d++) {
        float w = w1[(DOBS + d) * HH + c];
#pragma unroll
        for (int r = 0; r < TM; r++) acc[r] = fmaf(as[r*DA + d], w, acc[r]);
    }
    {
        float b1c = b1[c];
#pragma unroll
        for (int r4 = 0; r4 < 16; r4++) {
            float4 v;
            v.x = fmaxf(acc[4*r4+0] + b1c, 0.f);
            v.y = fmaxf(acc[4*r4+1] + b1c, 0.f);
            v.z = fmaxf(acc[4*r4+2] + b1c, 0.f);
            v.w = fmaxf(acc[4*r4+3] + b1c, 0.f);
            *(float4*)&h1sT[c*SPAD + 4*r4] = v;
        }
    }
    __syncthreads();

    // ---- Phase B: h2 col c; emit g2 = mask2 * w3[c]; q partials ----
#pragma unroll
    for (int r = 0; r < TM; r++) acc[r] = 0.f;
#pragma unroll 1
    for (int k0 = 0; k0 < HH; k0 += 8) {
        float wv[8];
#pragma unroll
        for (int u = 0; u < 8; u++) wv[u] = w2[(k0 + u) * HH + c];
#pragma unroll
        for (int u = 0; u < 8; u++) {
            const float4* hp = (const float4*)&h1sT[(k0 + u) * SPAD];
#pragma unroll
            for (int r4 = 0; r4 < 16; r4++) {
                float4 h = hp[r4];
                acc[4*r4+0] = fmaf(h.x, wv[u], acc[4*r4+0]);
                acc[4*r4+1] = fmaf(h.y, wv[u], acc[4*r4+1]);
                acc[4*r4+2] = fmaf(h.z, wv[u], acc[4*r4+2]);
                acc[4*r4+3] = fmaf(h.w, wv[u], acc[4*r4+3]);
            }
        }
    }
    {
        float b2c = b2[c], w3c = w3[c];
#pragma unroll 1
        for (int r = 0; r < TM; r++) {
            float pre  = acc[r] + b2c;
            float post = fmaxf(pre, 0.f);
            float qv   = post * w3c;
#pragma unroll
            for (int sh = 16; sh > 0; sh >>= 1) qv += __shfl_xor_sync(0xffffffffu, qv, sh);
            if (lane == 0) qpart[wid*TM + r] = qv;
            acc[r] = (pre > 0.f) ? w3c : 0.f;
        }
#pragma unroll
        for (int r4 = 0; r4 < 16; r4++) {
            float4 v = make_float4(acc[4*r4+0], acc[4*r4+1], acc[4*r4+2], acc[4*r4+3]);
            *(float4*)&g2sT[c*SPAD + 4*r4] = v;
        }
    }
    __syncthreads();

    // ---- Phase C: g1 col c = (g2 @ W2^T) * mask1 ----
#pragma unroll
    for (int r = 0; r < TM; r++) acc[r] = 0.f;
#pragma unroll 1
    for (int k0 = 0; k0 < HH; k0 += 8) {
        float wv[8];
#pragma unroll
        for (int u = 0; u < 8; u++) wv[u] = g_w2t[(k0 + u) * HH + c];
#pragma unroll
        for (int u = 0; u < 8; u++) {
            const float4* hp = (const float4*)&g2sT[(k0 + u) * SPAD];
#pragma unroll
            for (int r4 = 0; r4 < 16; r4++) {
                float4 h = hp[r4];
                acc[4*r4+0] = fmaf(h.x, wv[u], acc[4*r4+0]);
                acc[4*r4+1] = fmaf(h.y, wv[u], acc[4*r4+1]);
                acc[4*r4+2] = fmaf(h.z, wv[u], acc[4*r4+2]);
                acc[4*r4+3] = fmaf(h.w, wv[u], acc[4*r4+3]);
            }
        }
    }
#pragma unroll
    for (int r4 = 0; r4 < 16; r4++) {
        float4 h = *(const float4*)&h1sT[c*SPAD + 4*r4];
        g1rm[(4*r4+0)*HH + c] = (h.x > 0.f) ? acc[4*r4+0] : 0.f;
        g1rm[(4*r4+1)*HH + c] = (h.y > 0.f) ? acc[4*r4+1] : 0.f;
        g1rm[(4*r4+2)*HH + c] = (h.z > 0.f) ? acc[4*r4+2] : 0.f;
        g1rm[(4*r4+3)*HH + c] = (h.w > 0.f) ? acc[4*r4+3] : 0.f;
    }
    __syncthreads();

    // ---- Phase D: score = g1 @ W1_act^T, q finalize. warp wid owns rows wid*8..wid*8+7 ----
    float b3v = b3[0];
#pragma unroll 1
    for (int t = 0; t < 8; t++) {
        int r = wid*8 + t;
        int grow = row0 + r;
#pragma unroll
        for (int d = 0; d < DA; d++) {
            float s = 0.f;
#pragma unroll
            for (int i = 0; i < 8; i++) {
                int j = lane + 32*i;
                s = fmaf(g1rm[r*HH + j], w1[(DOBS + d)*HH + j], s);
            }
#pragma unroll
            for (int sh = 16; sh > 0; sh >>= 1) s += __shfl_xor_sync(0xffffffffu, s, sh);
            if (lane == 0) g_score[grow*DA + d] = s;
        }
        float q = (lane < 8) ? qpart[lane*TM + r] : 0.f;
#pragma unroll
        for (int sh = 4; sh > 0; sh >>= 1) q += __shfl_xor_sync(0xffffffffu, q, sh);
        if (lane == 0) q_out[grow] = q + b3v;
    }
}

// ---------------- SVGD update (one block per batch element) ----------------
__global__ void __launch_bounds__(256, 4) svgd_kernel(float* __restrict__ out_a,
                                                      float* __restrict__ out_logp)
{
    __shared__ float X[NN*DA], S[NN*DA], d2s[NN*NN], srt[NN*NN];
    __shared__ float gamma_sh;
    const int b = blockIdx.x;
    const int tid = threadIdx.x, lane = tid & 31, wid = tid >> 5;

    for (int idx = tid; idx < NN*DA; idx += 256) {
        X[idx] = g_abuf[b*NN*DA + idx];
        S[idx] = g_score[b*NN*DA + idx];
    }
    __syncthreads();

    // pairwise squared distances
    for (int e = tid; e < NN*NN; e += 256) {
        int i = e >> 5, j = e & 31;
        float s = 0.f;
#pragma unroll
        for (int d = 0; d < DA; d++) {
            float df = X[i*DA + d] - X[j*DA + d];
            s = fmaf(df, df, s);
        }
        d2s[e] = s; srt[e] = s;
    }
    __syncthreads();

    // bitonic sort of 1024 values (ascending) for the median
    for (int k = 2; k <= 1024; k <<= 1) {
        for (int j = k >> 1; j > 0; j >>= 1) {
#pragma unroll 1
            for (int t = tid; t < 512; t += 256) {
                int i = ((t & ~(j - 1)) << 1) | (t & (j - 1));
                int l = i | j;
                float av = srt[i], bv = srt[l];
                bool up = (i & k) == 0;
                if ((av > bv) == up) { srt[i] = bv; srt[l] = av; }
            }
            __syncthreads();
        }
    }
    if (tid == 0) {
        float med = 0.5f * (srt[511] + srt[512]);
        float h = med / LN32 + 1e-8f;
        gamma_sh = 1.f / (2.f * h);
    }
    __syncthreads();
    const float gamma = gamma_sh;
    const float tg = 2.f * gamma;

    // each warp handles 4 particles; lane = j index
#pragma unroll 1
    for (int ri = 0; ri < 4; ri++) {
        int i = wid*4 + ri;
        int j = lane;
        float d2ij = d2s[i*NN + j];
        float K = expf(-gamma * d2ij);
        float dotSD = 0.f;
        float vd[DA];
#pragma unroll
        for (int d = 0; d < DA; d++) {
            float df = X[i*DA + d] - X[j*DA + d];
            float sj = S[j*DA + d];
            dotSD = fmaf(df, sj, dotSD);
            vd[d] = K * fmaf(tg, df, sj);           // K*(S_jd + 2g*diff_d)
        }
#pragma unroll
        for (int d = 0; d < DA; d++) {
#pragma unroll
            for (int sh = 16; sh > 0; sh >>= 1) vd[d] += __shfl_xor_sync(0xffffffffu, vd[d], sh);
        }
        float t1 = -tg * K * dotSD;                  // K_grad . S_j
        float t2 = fmaf(tg * d2ij, K, -16.f * K);    // 2g d2 K - D*K
#pragma unroll
        for (int sh = 16; sh > 0; sh >>= 1) {
            t1 += __shfl_xor_sync(0xffffffffu, t1, sh);
            t2 += __shfl_xor_sync(0xffffffffu, t2, sh);
        }
        float tmp1 = t1 * (1.f/NN);
        float tmp2 = -tg * t2 * (1.f/NN);
        int grow = b*NN + i;
        if (lane == 0) {
            float lp = g_logp[grow] - LR * (tmp1 + tmp2);
            g_logp[grow] = lp;
            out_logp[grow] = lp;
        }
        if (lane < DA) {
            float av = X[i*DA + lane] + LR * (vd[lane] * (1.f/NN));
            av = fminf(fmaxf(av, -1.f), 1.f);
            g_abuf[grow*DA + lane] = av;
            out_a[grow*DA + lane]  = av;
        }
    }
}

// ---------------- launch ----------------
extern "C" void kernel_launch(void* const* d_in, const int* in_sizes, int n_in,
                              void* d_out, int out_size)
{
    const float* obs = (const float*)d_in[0];
    const float* a   = (const float*)d_in[1];
    const float* w1  = (const float*)d_in[2];
    const float* b1  = (const float*)d_in[3];
    const float* w2  = (const float*)d_in[4];
    const float* b2  = (const float*)d_in[5];
    const float* w3  = (const float*)d_in[6];
    const float* b3  = (const float*)d_in[7];

    float* out      = (float*)d_out;
    float* out_a    = out;                 // [B,N,16]
    float* out_logp = out + BN*DA;         // [B,N]
    float* out_q    = out + BN*DA + BN;    // [BN]

    cudaFuncSetAttribute(mlp_kernel, cudaFuncAttributeMaxDynamicSharedMemorySize, SMEM_BYTES);

    init_kernel<<<(BN*DA + 255)/256, 256>>>(a);
    {
        dim3 g(8, 8), blk(32, 8);
        transpose_w2<<<g, blk>>>(w2);
    }
    pre1_kernel<<<BN/TM, 256>>>(obs, w1);

    for (int s = 0; s < 3; s++) {
        mlp_kernel<<<BN/TM, 256, SMEM_BYTES>>>(w1, b1, w2, b2, w3, b3, out_q);
        svgd_kernel<<<BB, 256>>>(out_a, out_logp);
    }
}

// round 2
// speedup vs baseline: 3.6808x; 3.6808x over previous
#include <cuda_runtime.h>
#include <math.h>

#define BB   4096
#define NN   32
#define DA   16
#define DOBS 64
#define HH   256
#define BN   (BB*NN)
#define ROWS 128
#define NT   512
#define LN32 3.4657359027997265f
#define LR   0.1f

// ---------------- device scratch ----------------
__device__ float g_pre1[BN*HH];    // fragment-contiguous: [(cta*512+tid)*64 + frag*4 + j]
__device__ float g_abuf[BN*DA];
__device__ float g_score[BN*DA];
__device__ float g_logp[BN];
__device__ float g_w2t[HH*HH];

// ---------------- helpers ----------------
__device__ __forceinline__ unsigned f2tf(float x){
    unsigned u; asm("cvt.rna.tf32.f32 %0, %1;" : "=r"(u) : "f"(x)); return u;
}

__device__ __forceinline__ void mma8(float* c, const unsigned* a, unsigned b0, unsigned b1){
    asm volatile("mma.sync.aligned.m16n8k8.row.col.f32.tf32.tf32.f32 "
                 "{%0,%1,%2,%3},{%4,%5,%6,%7},{%8,%9},{%0,%1,%2,%3};\n"
                 : "+f"(c[0]),"+f"(c[1]),"+f"(c[2]),"+f"(c[3])
                 : "r"(a[0]),"r"(a[1]),"r"(a[2]),"r"(a[3]),"r"(b0),"r"(b1));
}

// packed slab: 16 k-values x 256 n.  uint index = kap*2048 + n*8 + tg*2 + half
// where kap=(klocal>>3), kk=klocal&7, tg=kk&3, half=kk>>2  (k = base + kap*8 + tg + half*4)
__device__ __forceinline__ void slab_ldg(const float* src, int ld, int k0g, int tid, float* r8){
#pragma unroll
    for (int i=0;i<8;i++){ int lin=i*NT+tid; r8[i] = src[(k0g+(lin>>8))*ld + (lin&255)]; }
}
__device__ __forceinline__ void slab_sts(unsigned* dst, int tid, const float* r8){
#pragma unroll
    for (int i=0;i<8;i++){
        int lin=i*NT+tid; int kl=lin>>8, n=lin&255, kk=kl&7;
        dst[(kl>>3)*2048 + n*8 + (kk&3)*2 + (kk>>2)] = f2tf(r8[i]);
    }
}

// 2 k-steps of mma over a packed slab. A from smem (tf32 bits), row stride lda.
__device__ __forceinline__ void mma_2ksteps(float acc[2][8][4], const unsigned* A, int lda, int kcA,
                                            const unsigned* slab, int wm, int wn, int g, int tg)
{
    const uint2* bf2 = (const uint2*)slab;
#pragma unroll
    for (int kap=0;kap<2;kap++){
        int kc = kcA + kap*8;
        unsigned a0[4], a1[4];
        int r0 = wm*32 + g;
        a0[0]=A[(r0   )*lda + kc+tg]; a0[1]=A[(r0+ 8)*lda + kc+tg];
        a0[2]=A[(r0   )*lda + kc+tg+4]; a0[3]=A[(r0+ 8)*lda + kc+tg+4];
        a1[0]=A[(r0+16)*lda + kc+tg]; a1[1]=A[(r0+24)*lda + kc+tg];
        a1[2]=A[(r0+16)*lda + kc+tg+4]; a1[3]=A[(r0+24)*lda + kc+tg+4];
#pragma unroll
        for (int ni=0;ni<8;ni++){
            int n = wn*64 + ni*8 + g;
            uint2 b = bf2[kap*1024 + n*4 + tg];
            mma8(acc[0][ni], a0, b.x, b.y);
            mma8(acc[1][ni], a1, b.x, b.y);
        }
    }
}

// ---------------- init ----------------
__global__ void init_kernel(const float* __restrict__ a)
{
    int i = blockIdx.x * 256 + threadIdx.x;
    if (i < BN*DA) g_abuf[i] = a[i];
    if (i < BN)    g_logp[i] = 0.f;
}

// ---------------- W2 transpose ----------------
__global__ void transpose_w2(const float* __restrict__ w2)
{
    __shared__ float t[32][33];
    int x  = blockIdx.x * 32 + threadIdx.x;
    int y0 = blockIdx.y * 32;
    for (int i = threadIdx.y; i < 32; i += 8)
        t[i][threadIdx.x] = w2[(y0 + i) * HH + x];
    __syncthreads();
    int x2 = blockIdx.y * 32 + threadIdx.x;
    for (int i = threadIdx.y; i < 32; i += 8)
        g_w2t[(blockIdx.x * 32 + i) * HH + x2] = t[threadIdx.x][i];
}

// ---------------- pre1 = obs @ W1[0:64,:]  (tensor, frag-contiguous output) ----------------
// smem: obs_s [128][68] tf32 (8704 u32) | slabs 4*4096 u32
#define PRE1_SMEM ((8704 + 4*4096) * 4)
__global__ void __launch_bounds__(NT,1) pre1_kernel(const float* __restrict__ obs,
                                                    const float* __restrict__ w1)
{
    extern __shared__ unsigned smu[];
    unsigned* obs_s = smu;
    unsigned* slabs = smu + 8704;
    const int tid = threadIdx.x;
    const int lane = tid & 31, wid = tid >> 5;
    const int g = lane >> 2, tg = lane & 3;
    const int wm = wid >> 2, wn = wid & 3;
    const int row0 = blockIdx.x * ROWS;

    // stage obs (128x64) tf32
#pragma unroll
    for (int i=0;i<16;i++){
        int lin = i*NT + tid; int r = lin>>6, c = lin&63;
        obs_s[r*68 + c] = f2tf(obs[(size_t)(row0 + r)*DOBS + c]);
    }
    // stage 4 slabs of W1 rows 0..63
    for (int s=0;s<4;s++){
        float r8[8];
        slab_ldg(w1, HH, s*16, tid, r8);
        slab_sts(slabs + s*4096, tid, r8);
    }
    __syncthreads();

    float acc[2][8][4];
#pragma unroll
    for (int mi=0;mi<2;mi++)
#pragma unroll
        for (int ni=0;ni<8;ni++)
#pragma unroll
            for (int j=0;j<4;j++) acc[mi][ni][j]=0.f;

    for (int s=0;s<4;s++)
        mma_2ksteps(acc, obs_s, 68, s*16, slabs + s*4096, wm, wn, g, tg);

    // write fragment-contiguous
    float4* pp = (float4*)(g_pre1 + ((size_t)blockIdx.x*NT + tid)*64);
#pragma unroll
    for (int mi=0;mi<2;mi++)
#pragma unroll
        for (int ni=0;ni<8;ni++)
            pp[mi*8+ni] = make_float4(acc[mi][ni][0],acc[mi][ni][1],acc[mi][ni][2],acc[mi][ni][3]);
}

// ---------------- fused MLP fwd+bwd (tensor) ----------------
// smem (u32 units):
//  OFF_H1  = 0       : h1s / g2s / g1s  [128][260]          33280
//  OFF_SL  = 33280   : slab double buf  2*4096  (also W1aT 256*24=6144, w1a slab 4096)
//  OFF_AUX = 41472   : as[128][20]=2560 / score_part 2*128*16=4096
//  OFF_QP  = 45568   : qpart [4][128] = 512
//  OFF_PB1 = 46080, OFF_PB2 = 46336, OFF_W3R = 46592, OFF_W3T = 46848   (end 47104)
#define OFF_H1  0
#define OFF_SL  33280
#define OFF_AUX 41472
#define OFF_QP  45568
#define OFF_PB1 46080
#define OFF_PB2 46336
#define OFF_W3R 46592
#define OFF_W3T 46848
#define MLP_SMEM (47104*4)

__global__ void __launch_bounds__(NT,1) mlp_kernel(
    const float* __restrict__ w1, const float* __restrict__ b1,
    const float* __restrict__ w2, const float* __restrict__ b2,
    const float* __restrict__ w3, const float* __restrict__ b3,
    float* __restrict__ q_out)
{
    extern __shared__ unsigned smu[];
    unsigned* sh1u = smu + OFF_H1;
    unsigned* slab = smu + OFF_SL;
    unsigned* asu  = smu + OFF_AUX;          // actions tf32, stride 20
    float*    spf  = (float*)(smu + OFF_AUX);// score partials (phase D)
    float*    qps  = (float*)(smu + OFF_QP);
    float*    b1s  = (float*)(smu + OFF_PB1);
    float*    b2s  = (float*)(smu + OFF_PB2);
    float*    w3r  = (float*)(smu + OFF_W3R);
    unsigned* w3t  = smu + OFF_W3T;

    const int tid = threadIdx.x;
    const int lane = tid & 31, wid = tid >> 5;
    const int g = lane >> 2, tg = lane & 3;
    const int wm = wid >> 2, wn = wid & 3;
    const int row0 = blockIdx.x * ROWS;

    // ---- stage actions, params, W1a slab ----
#pragma unroll
    for (int i=0;i<4;i++){
        int lin = i*NT + tid; int r = lin>>4, d = lin&15;
        asu[r*20 + d] = f2tf(g_abuf[(size_t)(row0 + r)*DA + d]);
    }
    if (tid < HH){
        b1s[tid] = b1[tid]; b2s[tid] = b2[tid];
        float v = w3[tid]; w3r[tid] = v; w3t[tid] = f2tf(v);
    }
    {
        float r8[8];
        slab_ldg(w1, HH, DOBS, tid, r8);   // W1 rows 64..79
        slab_sts(slab, tid, r8);
    }
    __syncthreads();

    float acc[2][8][4];

    // ---- Phase A: h1 = relu(pre1 + a@W1a + b1) ----
    {
        const float4* pp = (const float4*)(g_pre1 + ((size_t)blockIdx.x*NT + tid)*64);
#pragma unroll
        for (int mi=0;mi<2;mi++)
#pragma unroll
            for (int ni=0;ni<8;ni++){
                float4 v = pp[mi*8+ni];
                acc[mi][ni][0]=v.x; acc[mi][ni][1]=v.y; acc[mi][ni][2]=v.z; acc[mi][ni][3]=v.w;
            }
        mma_2ksteps(acc, asu, 20, 0, slab, wm, wn, g, tg);
    }
    unsigned long long mbits = 0ull;
    {
        int bit = 0;
#pragma unroll
        for (int mi=0;mi<2;mi++)
#pragma unroll
            for (int ni=0;ni<8;ni++){
                int n  = wn*64 + ni*8 + 2*tg;
                int r0 = wm*32 + mi*16 + g;
                float p0 = acc[mi][ni][0] + b1s[n];
                float p1 = acc[mi][ni][1] + b1s[n+1];
                float p2 = acc[mi][ni][2] + b1s[n];
                float p3 = acc[mi][ni][3] + b1s[n+1];
                mbits |= ((unsigned long long)(p0>0.f))<<(bit+0);
                mbits |= ((unsigned long long)(p1>0.f))<<(bit+1);
                mbits |= ((unsigned long long)(p2>0.f))<<(bit+2);
                mbits |= ((unsigned long long)(p3>0.f))<<(bit+3);
                uint2 v01 = make_uint2(f2tf(fmaxf(p0,0.f)), f2tf(fmaxf(p1,0.f)));
                uint2 v23 = make_uint2(f2tf(fmaxf(p2,0.f)), f2tf(fmaxf(p3,0.f)));
                *(uint2*)&sh1u[(r0  )*260 + n] = v01;
                *(uint2*)&sh1u[(r0+8)*260 + n] = v23;
                bit += 4;
            }
    }
    __syncthreads();

    // ---- Phase B: h2 grads. acc = h1 @ W2 ----
#pragma unroll
    for (int mi=0;mi<2;mi++)
#pragma unroll
        for (int ni=0;ni<8;ni++)
#pragma unroll
            for (int j=0;j<4;j++) acc[mi][ni][j]=0.f;
    {
        float r8[8];
        slab_ldg(w2, HH, 0, tid, r8);
        slab_sts(slab, tid, r8);
        __syncthreads();
        for (int s=0;s<16;s++){
            if (s<15) slab_ldg(w2, HH, (s+1)*16, tid, r8);
            mma_2ksteps(acc, sh1u, 260, s*16, slab + (s&1)*4096, wm, wn, g, tg);
            __syncthreads();
            if (s<15){ slab_sts(slab + ((s+1)&1)*4096, tid, r8); __syncthreads(); }
        }
    }
    // epilogue: q partials, g2 = (h2pre>0)?w3:0 -> sh1u
    {
        float qp[2][2] = {{0.f,0.f},{0.f,0.f}};
#pragma unroll
        for (int mi=0;mi<2;mi++)
#pragma unroll
            for (int ni=0;ni<8;ni++){
                int n  = wn*64 + ni*8 + 2*tg;
                int r0 = wm*32 + mi*16 + g;
                float p0 = acc[mi][ni][0] + b2s[n];
                float p1 = acc[mi][ni][1] + b2s[n+1];
                float p2 = acc[mi][ni][2] + b2s[n];
                float p3 = acc[mi][ni][3] + b2s[n+1];
                qp[mi][0] += fmaxf(p0,0.f)*w3r[n] + fmaxf(p1,0.f)*w3r[n+1];
                qp[mi][1] += fmaxf(p2,0.f)*w3r[n] + fmaxf(p3,0.f)*w3r[n+1];
                uint2 v01 = make_uint2((p0>0.f)?w3t[n]:0u, (p1>0.f)?w3t[n+1]:0u);
                uint2 v23 = make_uint2((p2>0.f)?w3t[n]:0u, (p3>0.f)?w3t[n+1]:0u);
                *(uint2*)&sh1u[(r0  )*260 + n] = v01;
                *(uint2*)&sh1u[(r0+8)*260 + n] = v23;
            }
#pragma unroll
        for (int mi=0;mi<2;mi++)
#pragma unroll
            for (int hi=0;hi<2;hi++){
                float v = qp[mi][hi];
                v += __shfl_xor_sync(0xffffffffu, v, 1);
                v += __shfl_xor_sync(0xffffffffu, v, 2);
                if (tg == 0) qps[wn*128 + wm*32 + mi*16 + g + 8*hi] = v;
            }
    }

    // ---- Phase C: g1 = (g2 @ W2^T) * mask1 ----
#pragma unroll
    for (int mi=0;mi<2;mi++)
#pragma unroll
        for (int ni=0;ni<8;ni++)
#pragma unroll
            for (int j=0;j<4;j++) acc[mi][ni][j]=0.f;
    {
        float r8[8];
        slab_ldg(g_w2t, HH, 0, tid, r8);
        slab_sts(slab, tid, r8);
        __syncthreads();
        for (int s=0;s<16;s++){
            if (s<15) slab_ldg(g_w2t, HH, (s+1)*16, tid, r8);
            mma_2ksteps(acc, sh1u, 260, s*16, slab + (s&1)*4096, wm, wn, g, tg);
            __syncthreads();
            if (s<15){ slab_sts(slab + ((s+1)&1)*4096, tid, r8); __syncthreads(); }
        }
    }
    // epilogue: masked g1 -> sh1u ; build W1aT (256x24) into slab area
    {
        int bit = 0;
#pragma unroll
        for (int mi=0;mi<2;mi++)
#pragma unroll
            for (int ni=0;ni<8;ni++){
                int n  = wn*64 + ni*8 + 2*tg;
                int r0 = wm*32 + mi*16 + g;
                unsigned u0 = ((mbits>>(bit+0))&1ull) ? f2tf(acc[mi][ni][0]) : 0u;
                unsigned u1 = ((mbits>>(bit+1))&1ull) ? f2tf(acc[mi][ni][1]) : 0u;
                unsigned u2 = ((mbits>>(bit+2))&1ull) ? f2tf(acc[mi][ni][2]) : 0u;
                unsigned u3 = ((mbits>>(bit+3))&1ull) ? f2tf(acc[mi][ni][3]) : 0u;
                *(uint2*)&sh1u[(r0  )*260 + n] = make_uint2(u0,u1);
                *(uint2*)&sh1u[(r0+8)*260 + n] = make_uint2(u2,u3);
                bit += 4;
            }
#pragma unroll
        for (int i=0;i<8;i++){
            int lin = i*NT + tid; int d = lin>>8, j = lin&255;
            slab[j*24 + d] = f2tf(w1[(size_t)(DOBS + d)*HH + j]);
        }
    }
    __syncthreads();

    // ---- Phase D: score = g1 @ W1a^T (M=128,N=16,K=256 split over 2 k-halves) ----
    {
        const int wk  = wid >> 3;       // 0/1: k half
        const int wm2 = wid & 7;        // 16-row tile
        float ad[2][4];
        ad[0][0]=ad[0][1]=ad[0][2]=ad[0][3]=0.f;
        ad[1][0]=ad[1][1]=ad[1][2]=ad[1][3]=0.f;
        int r0d = wm2*16 + g;
        for (int ks=0;ks<16;ks++){
            int kc = wk*128 + ks*8;
            unsigned a[4];
            a[0]=sh1u[(r0d  )*260 + kc+tg]; a[1]=sh1u[(r0d+8)*260 + kc+tg];
            a[2]=sh1u[(r0d  )*260 + kc+tg+4]; a[3]=sh1u[(r0d+8)*260 + kc+tg+4];
#pragma unroll
            for (int nf=0;nf<2;nf++){
                unsigned b0 = slab[(kc+tg  )*24 + nf*8 + g];
                unsigned b1 = slab[(kc+tg+4)*24 + nf*8 + g];
                mma8(ad[nf], a, b0, b1);
            }
        }
        __syncthreads();   // done reading sh1u/slab; spf aliases AUX (safe: asu dead)
#pragma unroll
        for (int nf=0;nf<2;nf++)
#pragma unroll
            for (int j=0;j<4;j++){
                int row = wm2*16 + g + 8*(j>>1);
                int col = nf*8 + 2*tg + (j&1);
                spf[wk*2048 + row*16 + col] = ad[nf][j];
            }
    }
    __syncthreads();

    // final: score + q
#pragma unroll
    for (int i=0;i<4;i++){
        int idx = i*NT + tid;
        int row = idx>>4, d = idx&15;
        g_score[(size_t)(row0 + row)*DA + d] = spf[idx] + spf[2048+idx];
    }
    if (tid < ROWS){
        float q = qps[tid] + qps[128+tid] + qps[256+tid] + qps[384+tid] + b3[0];
        q_out[row0 + tid] = q;
    }
}

// ---------------- SVGD update ----------------
__global__ void __launch_bounds__(256, 4) svgd_kernel(float* __restrict__ out_a,
                                                      float* __restrict__ out_logp)
{
    __shared__ float X[NN*DA], S[NN*DA], d2s[NN*NN], srt[NN*NN];
    __shared__ float gamma_sh;
    const int b = blockIdx.x;
    const int tid = threadIdx.x, lane = tid & 31, wid = tid >> 5;

    for (int idx = tid; idx < NN*DA; idx += 256) {
        X[idx] = g_abuf[b*NN*DA + idx];
        S[idx] = g_score[b*NN*DA + idx];
    }
    __syncthreads();

    for (int e = tid; e < NN*NN; e += 256) {
        int i = e >> 5, j = e & 31;
        float s = 0.f;
#pragma unroll
        for (int d = 0; d < DA; d++) {
            float df = X[i*DA + d] - X[j*DA + d];
            s = fmaf(df, df, s);
        }
        d2s[e] = s; srt[e] = s;
    }
    __syncthreads();

    for (int k = 2; k <= 1024; k <<= 1) {
        for (int j = k >> 1; j > 0; j >>= 1) {
#pragma unroll 1
            for (int t = tid; t < 512; t += 256) {
                int i = ((t & ~(j - 1)) << 1) | (t & (j - 1));
                int l = i | j;
                float av = srt[i], bv = srt[l];
                bool up = (i & k) == 0;
                if ((av > bv) == up) { srt[i] = bv; srt[l] = av; }
            }
            __syncthreads();
        }
    }
    if (tid == 0) {
        float med = 0.5f * (srt[511] + srt[512]);
        float h = med / LN32 + 1e-8f;
        gamma_sh = 1.f / (2.f * h);
    }
    __syncthreads();
    const float gamma = gamma_sh;
    const float tg2 = 2.f * gamma;

#pragma unroll 1
    for (int ri = 0; ri < 4; ri++) {
        int i = wid*4 + ri;
        int j = lane;
        float d2ij = d2s[i*NN + j];
        float K = expf(-gamma * d2ij);
        float dotSD = 0.f;
        float vd[DA];
#pragma unroll
        for (int d = 0; d < DA; d++) {
            float df = X[i*DA + d] - X[j*DA + d];
            float sj = S[j*DA + d];
            dotSD = fmaf(df, sj, dotSD);
            vd[d] = K * fmaf(tg2, df, sj);
        }
#pragma unroll
        for (int d = 0; d < DA; d++) {
#pragma unroll
            for (int sh = 16; sh > 0; sh >>= 1) vd[d] += __shfl_xor_sync(0xffffffffu, vd[d], sh);
        }
        float t1 = -tg2 * K * dotSD;
        float t2 = fmaf(tg2 * d2ij, K, -16.f * K);
#pragma unroll
        for (int sh = 16; sh > 0; sh >>= 1) {
            t1 += __shfl_xor_sync(0xffffffffu, t1, sh);
            t2 += __shfl_xor_sync(0xffffffffu, t2, sh);
        }
        float tmp1 = t1 * (1.f/NN);
        float tmp2 = -tg2 * t2 * (1.f/NN);
        int grow = b*NN + i;
        if (lane == 0) {
            float lp = g_logp[grow] - LR * (tmp1 + tmp2);
            g_logp[grow] = lp;
            out_logp[grow] = lp;
        }
        if (lane < DA) {
            float av = X[i*DA + lane] + LR * (vd[lane] * (1.f/NN));
            av = fminf(fmaxf(av, -1.f), 1.f);
            g_abuf[grow*DA + lane] = av;
            out_a[grow*DA + lane]  = av;
        }
    }
}

// ---------------- launch ----------------
extern "C" void kernel_launch(void* const* d_in, const int* in_sizes, int n_in,
                              void* d_out, int out_size)
{
    const float* obs = (const float*)d_in[0];
    const float* a   = (const float*)d_in[1];
    const float* w1  = (const float*)d_in[2];
    const float* b1  = (const float*)d_in[3];
    const float* w2  = (const float*)d_in[4];
    const float* b2  = (const float*)d_in[5];
    const float* w3  = (const float*)d_in[6];
    const float* b3  = (const float*)d_in[7];

    float* out      = (float*)d_out;
    float* out_a    = out;
    float* out_logp = out + BN*DA;
    float* out_q    = out + BN*DA + BN;

    static int attr_done = 0;
    cudaFuncSetAttribute(mlp_kernel,  cudaFuncAttributeMaxDynamicSharedMemorySize, MLP_SMEM);
    cudaFuncSetAttribute(pre1_kernel, cudaFuncAttributeMaxDynamicSharedMemorySize, PRE1_SMEM);
    (void)attr_done;

    init_kernel<<<(BN*DA + 255)/256, 256>>>(a);
    {
        dim3 gdim(8, 8), blk(32, 8);
        transpose_w2<<<gdim, blk>>>(w2);
    }
    pre1_kernel<<<BN/ROWS, NT, PRE1_SMEM>>>(obs, w1);

    for (int s = 0; s < 3; s++) {
        mlp_kernel<<<BN/ROWS, NT, MLP_SMEM>>>(w1, b1, w2, b2, w3, b3, out_q);
        svgd_kernel<<<BB, 256>>>(out_a, out_logp);
    }
}

// round 3
// speedup vs baseline: 3.8946x; 1.0581x over previous
#include <cuda_runtime.h>
#include <math.h>

#define BB   4096
#define NN   32
#define DA   16
#define DOBS 64
#define HH   256
#define BN   (BB*NN)
#define ROWS 128
#define NT   512
#define LDA_ACT 272
#define LN32 3.4657359027997265f
#define LR   0.1f

// ---------------- device scratch ----------------
__device__ float g_pre1[BN*HH];    // fragment-contiguous
__device__ float g_abuf[BN*DA];
__device__ float g_score[BN*DA];
__device__ float g_logp[BN];
__device__ float g_w2t[HH*HH];

// ---------------- helpers ----------------
__device__ __forceinline__ unsigned f2tf(float x){
    unsigned u; asm("cvt.rna.tf32.f32 %0, %1;" : "=r"(u) : "f"(x)); return u;
}
__device__ __forceinline__ void mma8(float* c, const unsigned* a, unsigned b0, unsigned b1){
    asm volatile("mma.sync.aligned.m16n8k8.row.col.f32.tf32.tf32.f32 "
                 "{%0,%1,%2,%3},{%4,%5,%6,%7},{%8,%9},{%0,%1,%2,%3};\n"
                 : "+f"(c[0]),"+f"(c[1]),"+f"(c[2]),"+f"(c[3])
                 : "r"(a[0]),"r"(a[1]),"r"(a[2]),"r"(a[3]),"r"(b0),"r"(b1));
}
// activation packed slot: within a 16-k group, value for k sits at
// slot = (k&3)*4 + ((k>>3)&1)*2 + ((k>>2)&1); groups are 16 u32 apart.
__device__ __forceinline__ int aslot16(int d){
    return ((d&3)<<2) | (((d>>3)&1)<<1) | ((d>>2)&1);
}
__device__ __forceinline__ int aslot(int n){
    return ((n>>4)<<4) | aslot16(n&15);
}

// B slab: 16 k x 256 n. uint4 per (n,tg): dst[n*16 + ((tg^(n&3))<<2)] =
//  {k=tg, k=tg+4, k=tg+8, k=tg+12} (tf32). Producer: 512 threads, 2 uint4 each.
__device__ __forceinline__ void fill_ldg(const float* __restrict__ src, int k0, int tid, float v[2][4]){
    int n = tid & 255, t0 = tid >> 8;
#pragma unroll
    for (int p=0;p<2;p++){
        int tgk = t0 + 2*p;
#pragma unroll
        for (int j=0;j<4;j++)
            v[p][j] = src[(size_t)(k0 + tgk + 4*j)*HH + n];
    }
}
__device__ __forceinline__ void fill_sts(unsigned* dst, int tid, const float v[2][4]){
    int n = tid & 255, t0 = tid >> 8;
#pragma unroll
    for (int p=0;p<2;p++){
        int tgk = t0 + 2*p;
        uint4 u = make_uint4(f2tf(v[p][0]), f2tf(v[p][1]), f2tf(v[p][2]), f2tf(v[p][3]));
        *(uint4*)&dst[n*16 + (((tgk ^ (n&3)))<<2)] = u;
    }
}

// one 16-k group of mma: A packed rows (stride lda), B packed slab
__device__ __forceinline__ void mma_16k(float acc[2][8][4], const unsigned* A, int lda, int kap2,
                                        const unsigned* slab, int wm, int wn, int g, int tg)
{
    const int r0 = wm*32 + g;
    const int ab = kap2*16 + tg*4;
    uint4 A0 = *(const uint4*)&A[(r0   )*lda + ab];
    uint4 A8 = *(const uint4*)&A[(r0+ 8)*lda + ab];
    uint4 A16= *(const uint4*)&A[(r0+16)*lda + ab];
    uint4 A24= *(const uint4*)&A[(r0+24)*lda + ab];
    unsigned a0k0[4] = {A0.x, A8.x, A0.y, A8.y};
    unsigned a0k1[4] = {A0.z, A8.z, A0.w, A8.w};
    unsigned a1k0[4] = {A16.x, A24.x, A16.y, A24.y};
    unsigned a1k1[4] = {A16.z, A24.z, A16.w, A24.w};
    const int sw = ((tg ^ (g&3))<<2);
#pragma unroll
    for (int ni=0;ni<8;ni++){
        int n = wn*64 + ni*8 + g;
        uint4 B = *(const uint4*)&slab[n*16 + sw];
        mma8(acc[0][ni], a0k0, B.x, B.y);
        mma8(acc[1][ni], a1k0, B.x, B.y);
        mma8(acc[0][ni], a0k1, B.z, B.w);
        mma8(acc[1][ni], a1k1, B.z, B.w);
    }
}

// ---------------- init ----------------
__global__ void init_kernel(const float* __restrict__ a)
{
    int i = blockIdx.x * 256 + threadIdx.x;
    if (i < BN*DA) g_abuf[i] = a[i];
    if (i < BN)    g_logp[i] = 0.f;
}

// ---------------- W2 transpose ----------------
__global__ void transpose_w2(const float* __restrict__ w2)
{
    __shared__ float t[32][33];
    int x  = blockIdx.x * 32 + threadIdx.x;
    int y0 = blockIdx.y * 32;
    for (int i = threadIdx.y; i < 32; i += 8)
        t[i][threadIdx.x] = w2[(y0 + i) * HH + x];
    __syncthreads();
    int x2 = blockIdx.y * 32 + threadIdx.x;
    for (int i = threadIdx.y; i < 32; i += 8)
        g_w2t[(blockIdx.x * 32 + i) * HH + x2] = t[threadIdx.x][i];
}

// ---------------- pre1 = obs @ W1[0:64,:] ----------------
// smem: obs packed [128][80] = 10240 u32 | 4 slabs * 4096
#define PRE1_SMEM ((10240 + 4*4096) * 4)
__global__ void __launch_bounds__(NT,1) pre1_kernel(const float* __restrict__ obs,
                                                    const float* __restrict__ w1)
{
    extern __shared__ unsigned smu[];
    unsigned* obs_s = smu;
    unsigned* slabs = smu + 10240;
    const int tid = threadIdx.x;
    const int lane = tid & 31, wid = tid >> 5;
    const int g = lane >> 2, tg = lane & 3;
    const int wm = wid >> 2, wn = wid & 3;
    const int row0 = blockIdx.x * ROWS;

#pragma unroll
    for (int i=0;i<16;i++){
        int lin = i*NT + tid; int r = lin>>6, c = lin&63;
        obs_s[r*80 + ((c>>4)<<4) + aslot16(c&15)] = f2tf(obs[(size_t)(row0 + r)*DOBS + c]);
    }
    for (int s=0;s<4;s++){
        float v[2][4];
        fill_ldg(w1, s*16, tid, v);
        fill_sts(slabs + s*4096, tid, v);
    }
    __syncthreads();

    float acc[2][8][4];
#pragma unroll
    for (int mi=0;mi<2;mi++)
#pragma unroll
        for (int ni=0;ni<8;ni++)
#pragma unroll
            for (int j=0;j<4;j++) acc[mi][ni][j]=0.f;

#pragma unroll
    for (int s=0;s<4;s++)
        mma_16k(acc, obs_s, 80, s, slabs + s*4096, wm, wn, g, tg);

    float4* pp = (float4*)(g_pre1 + ((size_t)blockIdx.x*NT + tid)*64);
#pragma unroll
    for (int mi=0;mi<2;mi++)
#pragma unroll
        for (int ni=0;ni<8;ni++)
            pp[mi*8+ni] = make_float4(acc[mi][ni][0],acc[mi][ni][1],acc[mi][ni][2],acc[mi][ni][3]);
}

// ---------------- fused MLP fwd+bwd ----------------
#define OFF_H1  0
#define OFF_SL  34816
#define OFF_AUX 43008
#define OFF_QP  47104
#define OFF_PB1 47616
#define OFF_PB2 47872
#define OFF_W3R 48128
#define OFF_W3T 48384
#define MLP_SMEM (48640*4)

__global__ void __launch_bounds__(NT,1) mlp_kernel(
    const float* __restrict__ w1, const float* __restrict__ b1,
    const float* __restrict__ w2, const float* __restrict__ b2,
    const float* __restrict__ w3, const float* __restrict__ b3,
    float* __restrict__ q_out)
{
    extern __shared__ unsigned smu[];
    unsigned* sh1u = smu + OFF_H1;           // activations [128][272] packed
    unsigned* slab = smu + OFF_SL;           // 2 x 4096 (also W1aT 256x24)
    unsigned* asu  = smu + OFF_AUX;          // actions packed [128][16]
    float*    spf  = (float*)(smu + OFF_AUX);// score partials (phase D)
    float*    qps  = (float*)(smu + OFF_QP);
    float*    b1s  = (float*)(smu + OFF_PB1);
    float*    b2s  = (float*)(smu + OFF_PB2);
    float*    w3r  = (float*)(smu + OFF_W3R);
    unsigned* w3t  = smu + OFF_W3T;

    const int tid = threadIdx.x;
    const int lane = tid & 31, wid = tid >> 5;
    const int g = lane >> 2, tg = lane & 3;
    const int wm = wid >> 2, wn = wid & 3;
    const int row0 = blockIdx.x * ROWS;

    // stage actions (packed), params, W1a slab into buf0
#pragma unroll
    for (int i=0;i<4;i++){
        int lin = i*NT + tid; int r = lin>>4, d = lin&15;
        asu[r*16 + aslot16(d)] = f2tf(g_abuf[(size_t)(row0 + r)*DA + d]);
    }
    if (tid < HH){
        b1s[tid] = b1[tid]; b2s[tid] = b2[tid];
        float v = w3[tid]; w3r[tid] = v; w3t[tid] = f2tf(v);
    }
    {
        float v[2][4];
        fill_ldg(w1, DOBS, tid, v);
        fill_sts(slab, tid, v);
    }
    __syncthreads();

    float acc[2][8][4];

    // ---- Phase A: h1 = relu(pre1 + a@W1a + b1) ----
    {
        const float4* pp = (const float4*)(g_pre1 + ((size_t)blockIdx.x*NT + tid)*64);
#pragma unroll
        for (int mi=0;mi<2;mi++)
#pragma unroll
            for (int ni=0;ni<8;ni++){
                float4 v = pp[mi*8+ni];
                acc[mi][ni][0]=v.x; acc[mi][ni][1]=v.y; acc[mi][ni][2]=v.z; acc[mi][ni][3]=v.w;
            }
        mma_16k(acc, asu, 16, 0, slab, wm, wn, g, tg);
    }
    unsigned long long mbits = 0ull;
    {
        int bit = 0;
#pragma unroll
        for (int mi=0;mi<2;mi++)
#pragma unroll
            for (int ni=0;ni<8;ni++){
                int n  = wn*64 + ni*8 + 2*tg;
                int r0 = wm*32 + mi*16 + g;
                int sl = aslot(n);
                float p0 = acc[mi][ni][0] + b1s[n];
                float p1 = acc[mi][ni][1] + b1s[n+1];
                float p2 = acc[mi][ni][2] + b1s[n];
                float p3 = acc[mi][ni][3] + b1s[n+1];
                mbits |= ((unsigned long long)(p0>0.f))<<(bit+0);
                mbits |= ((unsigned long long)(p1>0.f))<<(bit+1);
                mbits |= ((unsigned long long)(p2>0.f))<<(bit+2);
                mbits |= ((unsigned long long)(p3>0.f))<<(bit+3);
                sh1u[(r0  )*LDA_ACT + sl  ] = f2tf(fmaxf(p0,0.f));
                sh1u[(r0  )*LDA_ACT + sl+4] = f2tf(fmaxf(p1,0.f));
                sh1u[(r0+8)*LDA_ACT + sl  ] = f2tf(fmaxf(p2,0.f));
                sh1u[(r0+8)*LDA_ACT + sl+4] = f2tf(fmaxf(p3,0.f));
                bit += 4;
            }
    }
    __syncthreads();

    // ---- Phase B: acc = h1 @ W2 ----
#pragma unroll
    for (int mi=0;mi<2;mi++)
#pragma unroll
        for (int ni=0;ni<8;ni++)
#pragma unroll
            for (int j=0;j<4;j++) acc[mi][ni][j]=0.f;
    {
        float v[2][4];
        fill_ldg(w2, 0, tid, v);
        fill_sts(slab, tid, v);
        __syncthreads();
#pragma unroll 1
        for (int s=0;s<16;s++){
            if (s<15) fill_ldg(w2, (s+1)*16, tid, v);
            mma_16k(acc, sh1u, LDA_ACT, s, slab + (s&1)*4096, wm, wn, g, tg);
            if (s<15) fill_sts(slab + ((s+1)&1)*4096, tid, v);
            __syncthreads();
        }
    }
    // epilogue: q partials, g2 = (h2pre>0)?w3:0
    {
        float qp[2][2] = {{0.f,0.f},{0.f,0.f}};
#pragma unroll
        for (int mi=0;mi<2;mi++)
#pragma unroll
            for (int ni=0;ni<8;ni++){
                int n  = wn*64 + ni*8 + 2*tg;
                int r0 = wm*32 + mi*16 + g;
                int sl = aslot(n);
                float p0 = acc[mi][ni][0] + b2s[n];
                float p1 = acc[mi][ni][1] + b2s[n+1];
                float p2 = acc[mi][ni][2] + b2s[n];
                float p3 = acc[mi][ni][3] + b2s[n+1];
                qp[mi][0] += fmaxf(p0,0.f)*w3r[n] + fmaxf(p1,0.f)*w3r[n+1];
                qp[mi][1] += fmaxf(p2,0.f)*w3r[n] + fmaxf(p3,0.f)*w3r[n+1];
                sh1u[(r0  )*LDA_ACT + sl  ] = (p0>0.f)?w3t[n]:0u;
                sh1u[(r0  )*LDA_ACT + sl+4] = (p1>0.f)?w3t[n+1]:0u;
                sh1u[(r0+8)*LDA_ACT + sl  ] = (p2>0.f)?w3t[n]:0u;
                sh1u[(r0+8)*LDA_ACT + sl+4] = (p3>0.f)?w3t[n+1]:0u;
            }
#pragma unroll
        for (int mi=0;mi<2;mi++)
#pragma unroll
            for (int hi=0;hi<2;hi++){
                float v = qp[mi][hi];
                v += __shfl_xor_sync(0xffffffffu, v, 1);
                v += __shfl_xor_sync(0xffffffffu, v, 2);
                if (tg == 0) qps[wn*128 + wm*32 + mi*16 + g + 8*hi] = v;
            }
    }

    // ---- Phase C: g1 = (g2 @ W2^T) * mask1 ----
#pragma unroll
    for (int mi=0;mi<2;mi++)
#pragma unroll
        for (int ni=0;ni<8;ni++)
#pragma unroll
            for (int j=0;j<4;j++) acc[mi][ni][j]=0.f;
    {
        float v[2][4];
        fill_ldg(g_w2t, 0, tid, v);
        fill_sts(slab, tid, v);
        __syncthreads();
#pragma unroll 1
        for (int s=0;s<16;s++){
            if (s<15) fill_ldg(g_w2t, (s+1)*16, tid, v);
            mma_16k(acc, sh1u, LDA_ACT, s, slab + (s&1)*4096, wm, wn, g, tg);
            if (s<15) fill_sts(slab + ((s+1)&1)*4096, tid, v);
            __syncthreads();
        }
    }
    // epilogue: masked g1 -> sh1u ; build W1aT (256x24)
    {
        int bit = 0;
#pragma unroll
        for (int mi=0;mi<2;mi++)
#pragma unroll
            for (int ni=0;ni<8;ni++){
                int n  = wn*64 + ni*8 + 2*tg;
                int r0 = wm*32 + mi*16 + g;
                int sl = aslot(n);
                sh1u[(r0  )*LDA_ACT + sl  ] = ((mbits>>(bit+0))&1ull) ? f2tf(acc[mi][ni][0]) : 0u;
                sh1u[(r0  )*LDA_ACT + sl+4] = ((mbits>>(bit+1))&1ull) ? f2tf(acc[mi][ni][1]) : 0u;
                sh1u[(r0+8)*LDA_ACT + sl  ] = ((mbits>>(bit+2))&1ull) ? f2tf(acc[mi][ni][2]) : 0u;
                sh1u[(r0+8)*LDA_ACT + sl+4] = ((mbits>>(bit+3))&1ull) ? f2tf(acc[mi][ni][3]) : 0u;
                bit += 4;
            }
#pragma unroll
        for (int i=0;i<8;i++){
            int lin = i*NT + tid; int d = lin>>8, j = lin&255;
            slab[j*24 + d] = f2tf(w1[(size_t)(DOBS + d)*HH + j]);
        }
    }
    __syncthreads();

    // ---- Phase D: score = g1 @ W1a^T ----
    {
        const int wk  = wid >> 3;
        const int wm2 = wid & 7;
        float ad[2][4];
        ad[0][0]=ad[0][1]=ad[0][2]=ad[0][3]=0.f;
        ad[1][0]=ad[1][1]=ad[1][2]=ad[1][3]=0.f;
        int r0d = wm2*16 + g;
#pragma unroll 1
        for (int ks=0; ks<8; ks++){
            int kap2 = wk*8 + ks;
            uint4 A0 = *(const uint4*)&sh1u[(r0d  )*LDA_ACT + kap2*16 + tg*4];
            uint4 A8 = *(const uint4*)&sh1u[(r0d+8)*LDA_ACT + kap2*16 + tg*4];
            unsigned ak0[4] = {A0.x, A8.x, A0.y, A8.y};
            unsigned ak1[4] = {A0.z, A8.z, A0.w, A8.w};
            int kc = kap2*16;
#pragma unroll
            for (int nf=0;nf<2;nf++){
                unsigned b0 = slab[(kc+tg   )*24 + nf*8 + g];
                unsigned b1 = slab[(kc+tg+4 )*24 + nf*8 + g];
                mma8(ad[nf], ak0, b0, b1);
                unsigned c0 = slab[(kc+tg+8 )*24 + nf*8 + g];
                unsigned c1 = slab[(kc+tg+12)*24 + nf*8 + g];
                mma8(ad[nf], ak1, c0, c1);
            }
        }
        __syncthreads();   // sh1u/slab reads done; spf aliases AUX
#pragma unroll
        for (int nf=0;nf<2;nf++)
#pragma unroll
            for (int j=0;j<4;j++){
                int row = wm2*16 + g + 8*(j>>1);
                int col = nf*8 + 2*tg + (j&1);
                spf[wk*2048 + row*16 + col] = ad[nf][j];
            }
    }
    __syncthreads();

#pragma unroll
    for (int i=0;i<4;i++){
        int idx = i*NT + tid;
        int row = idx>>4, d = idx&15;
        g_score[(size_t)(row0 + row)*DA + d] = spf[idx] + spf[2048+idx];
    }
    if (tid < ROWS){
        float q = qps[tid] + qps[128+tid] + qps[256+tid] + qps[384+tid] + b3[0];
        q_out[row0 + tid] = q;
    }
}

// ---------------- SVGD update (radix-select median) ----------------
__global__ void __launch_bounds__(256, 4) svgd_kernel(float* __restrict__ out_a,
                                                      float* __restrict__ out_logp)
{
    __shared__ float X[NN*DA], S[NN*DA], d2s[NN*NN];
    __shared__ unsigned hist[2][16];
    __shared__ unsigned sh_prefix;
    __shared__ int sh_rank;
    __shared__ float gamma_sh;
    __shared__ unsigned w_cle[8], w_min[8];
    const int b = blockIdx.x;
    const int tid = threadIdx.x, lane = tid & 31, wid = tid >> 5;

    for (int idx = tid; idx < NN*DA; idx += 256) {
        X[idx] = g_abuf[b*NN*DA + idx];
        S[idx] = g_score[b*NN*DA + idx];
    }
    if (tid < 16) hist[0][tid] = 0;
    if (tid == 0){ sh_prefix = 0; sh_rank = 511; }
    __syncthreads();

    // pairwise d^2, 4 per thread (contiguous j)
    unsigned myv[4];
    {
        int i  = tid >> 3;
        int jb = (tid & 7) * 4;
#pragma unroll
        for (int ii=0; ii<4; ii++){
            int j = jb + ii;
            float s = 0.f;
#pragma unroll
            for (int d = 0; d < DA; d++) {
                float df = X[i*DA + d] - X[j*DA + d];
                s = fmaf(df, df, s);
            }
            d2s[i*NN + j] = s;
            myv[ii] = __float_as_uint(s);
        }
    }

    // radix select: rank 511 (0-indexed), MSB-first nibbles
    unsigned pmask = 0u;
#pragma unroll 1
    for (int rd = 0; rd < 8; rd++){
        int shift = 28 - rd*4;
        unsigned prefix = sh_prefix;
        if (tid < 16) hist[(rd+1)&1][tid] = 0;     // zero next round's buffer
#pragma unroll
        for (int ii=0; ii<4; ii++){
            if ((myv[ii] & pmask) == prefix)
                atomicAdd(&hist[rd&1][(myv[ii]>>shift)&15], 1u);
        }
        __syncthreads();
        if (tid == 0){
            int r = sh_rank; unsigned c = 0; int bsel = 0;
            for (int bb = 0; bb < 16; bb++){
                unsigned h = hist[rd&1][bb];
                if (c + h > (unsigned)r){ bsel = bb; break; }
                c += h;
            }
            sh_rank = r - (int)c;
            sh_prefix = prefix | ((unsigned)bsel << shift);
        }
        pmask = 0xFFFFFFFFu << shift;
        __syncthreads();
    }
    const unsigned v1 = sh_prefix;                  // bits of sorted[511]

    // sorted[512]: count <= v1 ; min of values > v1
    {
        int cle = 0; unsigned mab = 0xFFFFFFFFu;
#pragma unroll
        for (int ii=0; ii<4; ii++){
            if (myv[ii] <= v1) cle++;
            else mab = min(mab, myv[ii]);
        }
#pragma unroll
        for (int sh = 16; sh > 0; sh >>= 1){
            cle += __shfl_xor_sync(0xffffffffu, cle, sh);
            mab  = min(mab, __shfl_xor_sync(0xffffffffu, mab, sh));
        }
        if (lane == 0){ w_cle[wid] = (unsigned)cle; w_min[wid] = mab; }
        __syncthreads();
        if (tid == 0){
            unsigned t = 0, m = 0xFFFFFFFFu;
            for (int w = 0; w < 8; w++){ t += w_cle[w]; m = min(m, w_min[w]); }
            unsigned s512 = (t >= 513u) ? v1 : m;
            float med = 0.5f * (__uint_as_float(v1) + __uint_as_float(s512));
            float h = med / LN32 + 1e-8f;
            gamma_sh = 1.f / (2.f * h);
        }
        __syncthreads();
    }
    const float gamma = gamma_sh;
    const float tg2 = 2.f * gamma;

#pragma unroll 1
    for (int ri = 0; ri < 4; ri++) {
        int i = wid*4 + ri;
        int j = lane;
        float d2ij = d2s[i*NN + j];
        float K = expf(-gamma * d2ij);
        float dotSD = 0.f;
        float vd[DA];
#pragma unroll
        for (int d = 0; d < DA; d++) {
            float df = X[i*DA + d] - X[j*DA + d];
            float sj = S[j*DA + d];
            dotSD = fmaf(df, sj, dotSD);
            vd[d] = K * fmaf(tg2, df, sj);
        }
#pragma unroll
        for (int d = 0; d < DA; d++) {
#pragma unroll
            for (int sh = 16; sh > 0; sh >>= 1) vd[d] += __shfl_xor_sync(0xffffffffu, vd[d], sh);
        }
        float t1 = -tg2 * K * dotSD;
        float t2 = fmaf(tg2 * d2ij, K, -16.f * K);
#pragma unroll
        for (int sh = 16; sh > 0; sh >>= 1) {
            t1 += __shfl_xor_sync(0xffffffffu, t1, sh);
            t2 += __shfl_xor_sync(0xffffffffu, t2, sh);
        }
        float tmp1 = t1 * (1.f/NN);
        float tmp2 = -tg2 * t2 * (1.f/NN);
        int grow = b*NN + i;
        if (lane == 0) {
            float lp = g_logp[grow] - LR * (tmp1 + tmp2);
            g_logp[grow] = lp;
            out_logp[grow] = lp;
        }
        if (lane < DA) {
            float av = X[i*DA + lane] + LR * (vd[lane] * (1.f/NN));
            av = fminf(fmaxf(av, -1.f), 1.f);
            g_abuf[grow*DA + lane] = av;
            out_a[grow*DA + lane]  = av;
        }
    }
}

// ---------------- launch ----------------
extern "C" void kernel_launch(void* const* d_in, const int* in_sizes, int n_in,
                              void* d_out, int out_size)
{
    const float* obs = (const float*)d_in[0];
    const float* a   = (const float*)d_in[1];
    const float* w1  = (const float*)d_in[2];
    const float* b1  = (const float*)d_in[3];
    const float* w2  = (const float*)d_in[4];
    const float* b2  = (const float*)d_in[5];
    const float* w3  = (const float*)d_in[6];
    const float* b3  = (const float*)d_in[7];

    float* out      = (float*)d_out;
    float* out_a    = out;
    float* out_logp = out + BN*DA;
    float* out_q    = out + BN*DA + BN;

    cudaFuncSetAttribute(mlp_kernel,  cudaFuncAttributeMaxDynamicSharedMemorySize, MLP_SMEM);
    cudaFuncSetAttribute(pre1_kernel, cudaFuncAttributeMaxDynamicSharedMemorySize, PRE1_SMEM);

    init_kernel<<<(BN*DA + 255)/256, 256>>>(a);
    {
        dim3 gdim(8, 8), blk(32, 8);
        transpose_w2<<<gdim, blk>>>(w2);
    }
    pre1_kernel<<<BN/ROWS, NT, PRE1_SMEM>>>(obs, w1);

    for (int s = 0; s < 3; s++) {
        mlp_kernel<<<BN/ROWS, NT, MLP_SMEM>>>(w1, b1, w2, b2, w3, b3, out_q);
        svgd_kernel<<<BB, 256>>>(out_a, out_logp);
    }
}